// round 15
// baseline (speedup 1.0000x reference)
#include <cuda_runtime.h>
#include <cuda_fp16.h>
#include <math.h>
#include <stdint.h>

// ---------------------------------------------------------------------------
// VectorQuant: 512 CTAs (TM=256 rows), NT=256 (8 warps, warp tile 64x64 =>
// MMA:LDSM ratio 4.0 vs 2.7 — cuts the L1-pipe traffic ncu showed at 54%).
// Whole fp16 codebook (128KB) smem-resident. Score m' = (512e2+512) - acc
// (positive => uint-monotone), col idx in low 9 bits, IMNMX two-min; margin
// filter + R1-replica exact rescore keeps out0 bit-identical to R1.
// (Resubmission of R14 — container infra failed before execution.)
// ---------------------------------------------------------------------------

#define LVEC 128
#define KTOT 512
#define TM   256       // rows per CTA
#define NT   256       // 8 warps: 4 (M) x 2 (N), warp tile 64x64
#define NCHUNK 4       // N chunks of 128 cols
#define MARGIN_S 0.1536f
#define UNSC9 0.001953125f      // 2^-9, exact

typedef unsigned long long ull;

__device__ float        d_e2[KTOT];     // exact e2, R1 order
__device__ float        d_e2c[KTOT];    // 512*e2 + 512
__device__ unsigned int d_hist[KTOT];
__device__ __align__(16) uint16_t d_eh[KTOT * LVEC];   // fp16(e * 1024)

// smem byte offsets
#define OFF_A     0          // 65536: x fp16, swizzled (256 rows x 256B)
#define OFF_B     65536      // 131072: all 512 codes fp16, swizzled (resident)
#define OFF_SLOT  196608     // u32[256*5] = 5120
#define OFF_X2    201728     // float[256]
#define OFF_E2    202752     // float[512]
#define OFF_E2C   204800     // float[512]
#define OFF_IDX   206848     // int[256]
#define OFF_PX2   207872     // float[512]
#define OFF_FLAGC 209920     // int (+pad)
#define OFF_FLAGL 209936     // int[256]
#define OFF_RROW  210960     // ull[16]
#define OFF_DVAL  211088     // float[256]
#define SMEM_BYTES 212112
// rescore staging: XOR-swizzled 128 x 512B = 64KB, over dead A region
#define OFF_ESTG  0

__device__ __forceinline__ uint32_t smem_u32(const void* p) {
    uint32_t a;
    asm("{ .reg .u64 t; cvta.to.shared.u64 t, %1; cvt.u32.u64 %0, t; }"
        : "=r"(a) : "l"(p));
    return a;
}
__device__ __forceinline__ uint16_t f16_bits(float f) {
    __half h = __float2half_rn(f);
    return *reinterpret_cast<uint16_t*>(&h);
}
__device__ __forceinline__ uint32_t f16x2_bits(float lo, float hi) {
    uint32_t r;
    asm("cvt.rn.f16x2.f32 %0, %1, %2;" : "=r"(r) : "f"(hi), "f"(lo));
    return r;
}

#define CP_ASYNC16(sdst, gsrc) \
    asm volatile("cp.async.cg.shared.global [%0], [%1], 16;" \
                 :: "r"(sdst), "l"(gsrc) : "memory")
#define CP_COMMIT()  asm volatile("cp.async.commit_group;" ::: "memory")
#define CP_WAIT0()   asm volatile("cp.async.wait_group 0;" ::: "memory")

#define LDSM_X4(r0, r1, r2, r3, addr) \
    asm volatile("ldmatrix.sync.aligned.m8n8.x4.shared.b16 {%0,%1,%2,%3}, [%4];" \
                 : "=r"(r0), "=r"(r1), "=r"(r2), "=r"(r3) : "r"(addr))

#define MMA16816F16(c, a, b) \
    asm volatile("mma.sync.aligned.m16n8k16.row.col.f32.f16.f16.f32 " \
                 "{%0,%1,%2,%3}, {%4,%5,%6,%7}, {%8,%9}, {%0,%1,%2,%3};" \
                 : "+f"((c)[0]), "+f"((c)[1]), "+f"((c)[2]), "+f"((c)[3]) \
                 : "r"((a)[0]), "r"((a)[1]), "r"((a)[2]), "r"((a)[3]), \
                   "r"((b)[0]), "r"((b)[1]))

// ---------------- prep: fp16(e*1024), e2 (R1 order), 512e2+512, hist=0 -----
__global__ void __launch_bounds__(256) vq_prep(const float* __restrict__ emb) {
    int k = blockIdx.x * 8 + (threadIdx.x >> 5);
    int lane = threadIdx.x & 31;
    if (k < KTOT) {
        const float* e = emb + (size_t)k * LVEC;
        #pragma unroll
        for (int j = 0; j < 4; ++j) {
            int i = lane * 4 + j;
            d_eh[k * LVEC + i] = f16_bits(e[i] * 1024.0f);
        }
        if (lane == 0) {                  // e2 in R1's exact sequential order
            float s = 0.f;
            #pragma unroll 8
            for (int i = 0; i < LVEC; ++i) { float a = e[i]; s += a * a; }
            d_e2[k] = s;
            d_e2c[k] = s * 512.0f + 512.0f;
        }
    }
    int gt = blockIdx.x * 256 + threadIdx.x;
    if (gt < KTOT) d_hist[gt] = 0u;
}

// ---------------- main -----------------------------------------------------
__global__ void __launch_bounds__(NT, 1) vq_main(
    const float* __restrict__ x, const float* __restrict__ emb,
    float* __restrict__ out0, float* __restrict__ out1, float* __restrict__ out2)
{
    extern __shared__ unsigned char smem[];
    const uint32_t sb = smem_u32(smem);
    float* x2s   = (float*)(smem + OFF_X2);
    float* e2s   = (float*)(smem + OFF_E2);
    float* e2cs  = (float*)(smem + OFF_E2C);
    uint32_t* slots = (uint32_t*)(smem + OFF_SLOT);
    int*   sidx  = (int*)(smem + OFF_IDX);
    float* x2p   = (float*)(smem + OFF_PX2);
    int*   flagc = (int*)(smem + OFF_FLAGC);
    int*   flagl = (int*)(smem + OFF_FLAGL);
    ull*   rrow  = (ull*)(smem + OFF_RROW);
    float* dval  = (float*)(smem + OFF_DVAL);

    const int tid = threadIdx.x;
    const int wid = tid >> 5, lid = tid & 31;
    const int wm = wid >> 1, wn = wid & 1;          // 4 (M) x 2 (N)
    const int g = lid >> 3, li = lid & 7;
    const int gk = g >> 1, gm = g & 1;
    const int row0 = blockIdx.x * TM;

    if (tid == 0) *flagc = 0;
    for (int s = tid; s < KTOT; s += NT) { e2s[s] = d_e2[s]; e2cs[s] = d_e2c[s]; }

    // ---- fire ALL B cp.asyncs up front (overlaps x prologue) ----
    {
        const uint4* gh = (const uint4*)d_eh;
        #pragma unroll
        for (int it = 0; it < 32; ++it) {
            int f = it * NT + tid;          // 0..8191
            int r = f >> 4, u = f & 15;
            uint32_t off = (uint32_t)r * 256 + (uint32_t)((u ^ (r & 7)) << 4);
            CP_ASYNC16(sb + OFF_B + off, gh + f);
        }
        CP_COMMIT();
    }

    // ---- load x tile (coalesced), convert fp16 (packed), swizzled STS ----
    {
        const float4* x4 = (const float4*)x + (size_t)row0 * 32;
        #pragma unroll
        for (int it = 0; it < 16; ++it) {
            int f = it * NT + tid;          // 0..4095
            int r = f >> 4, u = f & 15;
            float4 v0 = x4[r * 32 + u * 2];
            float4 v1 = x4[r * 32 + u * 2 + 1];
            uint4 hw = make_uint4(f16x2_bits(v0.x, v0.y), f16x2_bits(v0.z, v0.w),
                                  f16x2_bits(v1.x, v1.y), f16x2_bits(v1.z, v1.w));
            uint32_t off = (uint32_t)r * 256 + (uint32_t)((u ^ (r & 7)) << 4);
            *(uint4*)(smem + OFF_A + off) = hw;
        }
    }

    // ---- x2: EXACT replication of R1's arithmetic order ----
    {
        const float4* x4 = (const float4*)x + (size_t)row0 * 32;
        #pragma unroll
        for (int rep = 0; rep < 2; ++rep) {
            int idx = rep * NT + tid;       // 0..511
            int r = idx >> 1, b = idx & 1;
            float px2 = 0.f;
            #pragma unroll
            for (int i = 0; i < 16; ++i) {
                float4 v = x4[(size_t)r * 32 + b + i * 2];
                px2 += v.x * v.x; px2 += v.y * v.y;
                px2 += v.z * v.z; px2 += v.w * v.w;
            }
            x2p[idx] = px2;
        }
    }
    CP_WAIT0();
    __syncthreads();                        // A, B, e2 tables, px2 all visible
    x2s[tid] = x2p[2 * tid] + x2p[2 * tid + 1];   // tid == row (NT == TM)

    // ---- per-lane ldmatrix base addresses (warp tile 64x64) ----
    uint32_t aAd[4], bAd[4];
    #pragma unroll
    for (int mt = 0; mt < 4; ++mt)
        aAd[mt] = sb + OFF_A + (uint32_t)(wm * 64 + mt * 16 + li + gm * 8) * 256;
    #pragma unroll
    for (int nb = 0; nb < 4; ++nb)
        bAd[nb] = sb + OFF_B + (uint32_t)(wn * 64 + nb * 16 + li + gk * 8) * 256;

    const int qr = lid >> 2, qc = lid & 3;

    // cross-chunk two-min keys (8 row-slots: mt*2+rh), 32-bit
    uint32_t key1[8], key2[8];
    #pragma unroll
    for (int s = 0; s < 8; ++s) { key1[s] = ~0u; key2[s] = ~0u; }

    // ---- barrier-free mainloop: 4 chunks x (8 ksteps LDSM+MMA) + scoring ----
    for (int ch = 0; ch < NCHUNK; ++ch) {
        const uint32_t bOff = (uint32_t)ch * 32768;

        float acc[4][8][4];
        #pragma unroll
        for (int mt = 0; mt < 4; ++mt)
            #pragma unroll
            for (int nt = 0; nt < 8; ++nt)
                #pragma unroll
                for (int c = 0; c < 4; ++c) acc[mt][nt][c] = 0.f;

        #pragma unroll
        for (int kk = 0; kk < 8; ++kk) {
            uint32_t kswzA = (uint32_t)(((kk * 2 + gk) ^ li) << 4);
            uint32_t kswzB = (uint32_t)(((kk * 2 + gm) ^ li) << 4);
            uint32_t ah[4][4], bh[8][2];
            #pragma unroll
            for (int mt = 0; mt < 4; ++mt)
                LDSM_X4(ah[mt][0], ah[mt][1], ah[mt][2], ah[mt][3],
                        aAd[mt] + kswzA);
            #pragma unroll
            for (int nb = 0; nb < 4; ++nb) {
                uint32_t r0, r1, r2, r3;
                LDSM_X4(r0, r1, r2, r3, bAd[nb] + bOff + kswzB);
                bh[2 * nb][0] = r0; bh[2 * nb][1] = r1;
                bh[2 * nb + 1][0] = r2; bh[2 * nb + 1][1] = r3;
            }
            #pragma unroll
            for (int mt = 0; mt < 4; ++mt)
                #pragma unroll
                for (int nt = 0; nt < 8; ++nt)
                    MMA16816F16(acc[mt][nt], ah[mt], bh[nt]);
        }

        // ---- scoring: m' = e2c - acc (positive), col in low 9 bits ----
        const int colb = ch * 128 + wn * 64 + qc * 2;
        float he2c[16];
        #pragma unroll
        for (int nt = 0; nt < 8; ++nt) {
            he2c[nt * 2]     = e2cs[colb + nt * 8];
            he2c[nt * 2 + 1] = e2cs[colb + nt * 8 + 1];
        }
        #pragma unroll
        for (int mt = 0; mt < 4; ++mt) {
            #pragma unroll
            for (int rh = 0; rh < 2; ++rh) {
                const int s = mt * 2 + rh;
                uint32_t k1 = key1[s], k2 = key2[s];
                #pragma unroll
                for (int nt = 0; nt < 8; ++nt) {
                    #pragma unroll
                    for (int cc = 0; cc < 2; ++cc) {
                        float v = __fsub_rn(he2c[nt * 2 + cc],
                                            acc[mt][nt][rh * 2 + cc]);
                        uint32_t k = (__float_as_uint(v) & 0xFFFFFE00u)
                                   | (uint32_t)(colb + nt * 8 + cc);
                        k2 = umin(k2, umax(k1, k));
                        k1 = umin(k1, k);
                    }
                }
                key1[s] = k1; key2[s] = k2;
            }
        }
    }

    // ---- shuffle-merge across qc lanes, write slots ----
    #pragma unroll
    for (int s = 0; s < 8; ++s) {
        uint32_t k1 = key1[s], k2 = key2[s];
        #pragma unroll
        for (int m = 1; m <= 2; m <<= 1) {
            uint32_t o1 = __shfl_xor_sync(0xffffffffu, k1, m);
            uint32_t o2 = __shfl_xor_sync(0xffffffffu, k2, m);
            k2 = umin(umax(k1, o1), umin(k2, o2));
            k1 = umin(k1, o1);
        }
        if (qc == 0) {
            int row = wm * 64 + (s >> 1) * 16 + qr + (s & 1) * 8;
            slots[row * 5 + wn * 2 + 0] = k1;
            slots[row * 5 + wn * 2 + 1] = k2;
        }
    }
    __syncthreads();

    // ---- per-row merge of 4 slot keys; margin test; d recovery ----
    {
        uint32_t k1 = ~0u, k2 = ~0u;
        #pragma unroll
        for (int i = 0; i < 4; ++i) {
            uint32_t k = slots[tid * 5 + i];
            k2 = umin(k2, umax(k1, k));
            k1 = umin(k1, k);
        }
        sidx[tid] = (int)(k1 & 0x1FFu);
        float m1 = __uint_as_float(k1 & 0xFFFFFE00u);
        float m2 = __uint_as_float(k2 & 0xFFFFFE00u);
        dval[tid] = __fmaf_rn(__fsub_rn(m1, 512.0f), UNSC9, x2s[tid]);
        if (!(m2 - m1 > MARGIN_S)) {
            int pos = atomicAdd(flagc, 1);
            flagl[pos] = tid;
        }
    }
    __syncthreads();

    // ---- exact rescore (R1-replica) — staging in dead A region ----
    const int nflag = *flagc;
    for (int base = 0; base < nflag; base += 16) {
        const int gcount = min(nflag - base, 16);
        if (tid < 16) rrow[tid] = ~0ull;
        for (int cc2 = 0; cc2 < 4; ++cc2) {
            __syncthreads();
            for (int i = tid; i < 128 * 32; i += NT) {
                int r = i >> 5, c4 = i & 31;
                float4 v = ((const float4*)emb)[(size_t)(cc2 * 128 + r) * 32 + c4];
                *(float4*)(smem + OFF_ESTG + r * 512 + ((c4 ^ (r & 31)) << 4)) = v;
            }
            __syncthreads();
            for (int p = tid; p < gcount * 128; p += NT) {
                int fi = p >> 7, c = p & 127;
                int r = flagl[base + fi];
                const float2* xr = (const float2*)x
                                 + (size_t)(row0 + r) * 64;   // warp-broadcast
                const unsigned char* eb = smem + OFF_ESTG + (size_t)c * 512;
                const uint32_t cm = (uint32_t)(c & 31);
                float evn = 0.f, od = 0.f;
                #pragma unroll 8
                for (int l = 0; l < 64; ++l) {
                    float2 xv = xr[l];
                    float2 ev = *(const float2*)(eb
                        + (((uint32_t)(l >> 1) ^ cm) << 4) + (l & 1) * 8);
                    evn = __fmaf_rn(xv.x, ev.x, evn);
                    od  = __fmaf_rn(xv.y, ev.y, od);
                }
                float dot = __fadd_rn(evn, od);
                float d = __fadd_rn(__fsub_rn(x2s[r], __fmul_rn(2.0f, dot)),
                                    e2s[cc2 * 128 + c]);
                ull k = ((ull)__float_as_uint(d) << 32)
                      | (unsigned)(cc2 * 128 + c);
                atomicMin(&rrow[fi], k);
            }
        }
        __syncthreads();
        if (tid < gcount) {
            int r = flagl[base + tid];
            sidx[r] = (int)(rrow[tid] & 0xffffffffu);
            dval[r] = __uint_as_float((uint32_t)(rrow[tid] >> 32));
        }
        __syncthreads();
    }

    // ---- histogram: direct global RED ----
    atomicAdd(&d_hist[sidx[tid]], 1u);      // tid == row

    // ---- out0: coalesced gather ----
    #pragma unroll
    for (int it = 0; it < 32; ++it) {
        int f = it * NT + tid;              // 0..8191
        int r = f >> 5, c = f & 31;
        float4 e = ((const float4*)emb)[(size_t)sidx[r] * 32 + c];
        ((float4*)out0)[(size_t)(row0 + r) * 32 + c] = e;
    }

    // ---- out1/out2 from recovered d ----
    {
        float s = dval[tid];
        out1[row0 + tid] = s;
        out2[row0 + tid] = s;
    }
}

// ---------------- entropy --------------------------------------------------
__global__ void vq_entropy(float* __restrict__ out_ent, float invRows) {
    __shared__ float red[KTOT];
    int t = threadIdx.x;
    float c = (float)d_hist[t];
    float p = c * invRows;
    red[t] = (p > 0.f) ? p * logf(p) : 0.f;
    __syncthreads();
    #pragma unroll
    for (int s = KTOT / 2; s > 0; s >>= 1) {
        if (t < s) red[t] += red[t + s];
        __syncthreads();
    }
    if (t == 0) *out_ent = -red[0];
}

// Profiler-alignment no-op: ncu captures launch index 3; with the order
// [nop, nop, prep, main, entropy], index 3 = vq_main.
__global__ void vq_nop() {}

extern "C" void kernel_launch(void* const* d_in, const int* in_sizes, int n_in,
                              void* d_out, int out_size)
{
    const float* x   = (const float*)d_in[0];
    const float* emb = (const float*)d_in[1];
    const int rows = in_sizes[0] / LVEC;

    float* out0 = (float*)d_out;
    float* out1 = out0 + (size_t)rows * LVEC;
    float* out2 = out1 + rows;
    float* oent = out2 + rows;

    cudaFuncSetAttribute(vq_main, cudaFuncAttributeMaxDynamicSharedMemorySize,
                         SMEM_BYTES);

    vq_nop<<<1, 32>>>();
    vq_nop<<<1, 32>>>();
    vq_prep<<<64, 256>>>(emb);
    vq_main<<<rows / TM, NT, SMEM_BYTES>>>(x, emb, out0, out1, out2);
    vq_entropy<<<1, KTOT>>>(oent, 1.0f / (float)rows);
}

// round 16
// speedup vs baseline: 1.3810x; 1.3810x over previous
#include <cuda_runtime.h>
#include <cuda_fp16.h>
#include <math.h>
#include <stdint.h>

// ---------------------------------------------------------------------------
// VectorQuant: occupancy play. TM=128, NT=256 (8 warps, 4M x 2N, warp tile
// 32x32/chunk, acc=32 regs), __launch_bounds__(256,3) => 24 warps/SM (regfile
// was the 16-warp cap at 128 regs). Double-buffered cp.async B ring (8 x 64
// cols). Score m' = (512e2+512) - acc (positive => uint-monotone), col idx in
// low 9 bits, IMNMX two-min; margin filter + R1-replica exact rescore keeps
// out0 bit-identical to R1.
// ---------------------------------------------------------------------------

#define LVEC 128
#define KTOT 512
#define TM   128       // rows per CTA
#define NT   256       // 8 warps: 4 (M) x 2 (N)
#define NCH  64        // codes per chunk
#define NCHUNK 8
#define MARGIN_S 0.1536f
#define UNSC9 0.001953125f      // 2^-9, exact

typedef unsigned long long ull;

__device__ float        d_e2[KTOT];     // exact e2, R1 order
__device__ float        d_e2c[KTOT];    // 512*e2 + 512
__device__ unsigned int d_hist[KTOT];
__device__ __align__(16) uint16_t d_eh[KTOT * LVEC];   // fp16(e * 1024)

// smem byte offsets
#define OFF_A     0          // 32768: x fp16, swizzled (128 rows x 256B)
#define OFF_B     32768      // 2 x 16384 double-buffered code chunks
#define OFF_SLOT  65536      // u32[128*5] = 2560
#define OFF_X2    68096      // float[128]
#define OFF_E2    68608      // float[512]
#define OFF_E2C   70656      // float[512]
#define OFF_IDX   72704      // int[128]
#define OFF_PX2   73216      // float[256]
#define OFF_FLAGC 74240      // int (+pad)
#define OFF_FLAGL 74248      // int[128]
#define OFF_RROW  74760      // ull[16]
#define OFF_DVAL  74888      // float[128]
#define SMEM_BYTES 75520
// rescore staging: XOR-swizzled 128 x 512B = 64KB over dead A+B regions
#define OFF_ESTG  0

__device__ __forceinline__ uint32_t smem_u32(const void* p) {
    uint32_t a;
    asm("{ .reg .u64 t; cvta.to.shared.u64 t, %1; cvt.u32.u64 %0, t; }"
        : "=r"(a) : "l"(p));
    return a;
}
__device__ __forceinline__ uint16_t f16_bits(float f) {
    __half h = __float2half_rn(f);
    return *reinterpret_cast<uint16_t*>(&h);
}
__device__ __forceinline__ uint32_t f16x2_bits(float lo, float hi) {
    uint32_t r;
    asm("cvt.rn.f16x2.f32 %0, %1, %2;" : "=r"(r) : "f"(hi), "f"(lo));
    return r;
}

#define CP_ASYNC16(sdst, gsrc) \
    asm volatile("cp.async.cg.shared.global [%0], [%1], 16;" \
                 :: "r"(sdst), "l"(gsrc) : "memory")
#define CP_COMMIT()  asm volatile("cp.async.commit_group;" ::: "memory")
#define CP_WAIT1()   asm volatile("cp.async.wait_group 1;" ::: "memory")

#define LDSM_X4(r0, r1, r2, r3, addr) \
    asm volatile("ldmatrix.sync.aligned.m8n8.x4.shared.b16 {%0,%1,%2,%3}, [%4];" \
                 : "=r"(r0), "=r"(r1), "=r"(r2), "=r"(r3) : "r"(addr))

#define MMA16816F16(c, a, b) \
    asm volatile("mma.sync.aligned.m16n8k16.row.col.f32.f16.f16.f32 " \
                 "{%0,%1,%2,%3}, {%4,%5,%6,%7}, {%8,%9}, {%0,%1,%2,%3};" \
                 : "+f"((c)[0]), "+f"((c)[1]), "+f"((c)[2]), "+f"((c)[3]) \
                 : "r"((a)[0]), "r"((a)[1]), "r"((a)[2]), "r"((a)[3]), \
                   "r"((b)[0]), "r"((b)[1]))

// ---------------- prep: fp16(e*1024), e2 (R1 order), 512e2+512, hist=0 -----
__global__ void __launch_bounds__(256) vq_prep(const float* __restrict__ emb) {
    int k = blockIdx.x * 8 + (threadIdx.x >> 5);
    int lane = threadIdx.x & 31;
    if (k < KTOT) {
        const float* e = emb + (size_t)k * LVEC;
        #pragma unroll
        for (int j = 0; j < 4; ++j) {
            int i = lane * 4 + j;
            d_eh[k * LVEC + i] = f16_bits(e[i] * 1024.0f);
        }
        if (lane == 0) {                  // e2 in R1's exact sequential order
            float s = 0.f;
            #pragma unroll 8
            for (int i = 0; i < LVEC; ++i) { float a = e[i]; s += a * a; }
            d_e2[k] = s;
            d_e2c[k] = s * 512.0f + 512.0f;
        }
    }
    int gt = blockIdx.x * 256 + threadIdx.x;
    if (gt < KTOT) d_hist[gt] = 0u;
}

// ---------------- main -----------------------------------------------------
__global__ void __launch_bounds__(NT, 3) vq_main(
    const float* __restrict__ x, const float* __restrict__ emb,
    float* __restrict__ out0, float* __restrict__ out1, float* __restrict__ out2)
{
    extern __shared__ unsigned char smem[];
    const uint32_t sb = smem_u32(smem);
    float* x2s   = (float*)(smem + OFF_X2);
    float* e2s   = (float*)(smem + OFF_E2);
    float* e2cs  = (float*)(smem + OFF_E2C);
    uint32_t* slots = (uint32_t*)(smem + OFF_SLOT);
    int*   sidx  = (int*)(smem + OFF_IDX);
    float* x2p   = (float*)(smem + OFF_PX2);
    int*   flagc = (int*)(smem + OFF_FLAGC);
    int*   flagl = (int*)(smem + OFF_FLAGL);
    ull*   rrow  = (ull*)(smem + OFF_RROW);
    float* dval  = (float*)(smem + OFF_DVAL);

    const int tid = threadIdx.x;
    const int wid = tid >> 5, lid = tid & 31;
    const int wm = wid >> 1, wn = wid & 1;          // 4 (M) x 2 (N)
    const int g = lid >> 3, li = lid & 7;
    const int gk = g >> 1, gm = g & 1;
    const int row0 = blockIdx.x * TM;

    if (tid == 0) *flagc = 0;
    for (int s = tid; s < KTOT; s += NT) { e2s[s] = d_e2[s]; e2cs[s] = d_e2c[s]; }

    // ---- prefetch first two B chunks ----
    {
        const uint4* gh = (const uint4*)d_eh;
        #pragma unroll
        for (int it = 0; it < 4; ++it) {
            int f = it * NT + tid;          // 0..1023
            int r = f >> 4, u = f & 15;
            uint32_t off = (uint32_t)r * 256 + (uint32_t)((u ^ (r & 7)) << 4);
            CP_ASYNC16(sb + OFF_B + off, gh + f);
        }
        CP_COMMIT();
        gh += NCH * 16;
        #pragma unroll
        for (int it = 0; it < 4; ++it) {
            int f = it * NT + tid;
            int r = f >> 4, u = f & 15;
            uint32_t off = (uint32_t)r * 256 + (uint32_t)((u ^ (r & 7)) << 4);
            CP_ASYNC16(sb + OFF_B + 16384 + off, gh + f);
        }
        CP_COMMIT();
    }

    // ---- load x tile (coalesced), convert fp16 (packed), swizzled STS ----
    {
        const float4* x4 = (const float4*)x + (size_t)row0 * 32;
        #pragma unroll
        for (int it = 0; it < 8; ++it) {
            int f = it * NT + tid;          // 0..2047
            int r = f >> 4, u = f & 15;
            float4 v0 = x4[r * 32 + u * 2];
            float4 v1 = x4[r * 32 + u * 2 + 1];
            uint4 hw = make_uint4(f16x2_bits(v0.x, v0.y), f16x2_bits(v0.z, v0.w),
                                  f16x2_bits(v1.x, v1.y), f16x2_bits(v1.z, v1.w));
            uint32_t off = (uint32_t)r * 256 + (uint32_t)((u ^ (r & 7)) << 4);
            *(uint4*)(smem + OFF_A + off) = hw;
        }
    }

    // ---- x2: EXACT replication of R1's arithmetic order ----
    {
        const float4* x4 = (const float4*)x + (size_t)row0 * 32;
        int r = tid >> 1, b = tid & 1;
        float px2 = 0.f;
        #pragma unroll
        for (int i = 0; i < 16; ++i) {
            float4 v = x4[(size_t)r * 32 + b + i * 2];
            px2 += v.x * v.x; px2 += v.y * v.y; px2 += v.z * v.z; px2 += v.w * v.w;
        }
        x2p[tid] = px2;
    }
    __syncthreads();
    if (tid < TM) x2s[tid] = x2p[2 * tid] + x2p[2 * tid + 1];

    // ---- per-lane ldmatrix base addresses (warp tile 32x32 per chunk) ----
    uint32_t aAd[2], bOffRow[2];
    #pragma unroll
    for (int mt = 0; mt < 2; ++mt)
        aAd[mt] = sb + OFF_A + (uint32_t)(wm * 32 + mt * 16 + li + gm * 8) * 256;
    #pragma unroll
    for (int nb = 0; nb < 2; ++nb)
        bOffRow[nb] = (uint32_t)(wn * 32 + nb * 16 + li + gk * 8) * 256;

    const int qr = lid >> 2, qc = lid & 3;

    // cross-chunk two-min keys (4 row-slots: mt*2+rh), 32-bit
    uint32_t key1[4] = {~0u, ~0u, ~0u, ~0u}, key2[4] = {~0u, ~0u, ~0u, ~0u};

    // ---- mainloop: 8 chunks of 64 cols, double-buffered cp.async ----
    for (int ch = 0; ch < NCHUNK; ++ch) {
        CP_WAIT1();              // chunk ch resident in buf[ch&1]
        __syncthreads();

        const uint32_t bBase = sb + OFF_B + (uint32_t)(ch & 1) * 16384;

        float acc[2][4][4];
        #pragma unroll
        for (int mt = 0; mt < 2; ++mt)
            #pragma unroll
            for (int nt = 0; nt < 4; ++nt)
                #pragma unroll
                for (int c = 0; c < 4; ++c) acc[mt][nt][c] = 0.f;

        #pragma unroll
        for (int kk = 0; kk < 8; ++kk) {
            uint32_t kswzA = (uint32_t)(((kk * 2 + gk) ^ li) << 4);
            uint32_t kswzB = (uint32_t)(((kk * 2 + gm) ^ li) << 4);
            uint32_t ah[2][4], bh[4][2];
            #pragma unroll
            for (int mt = 0; mt < 2; ++mt)
                LDSM_X4(ah[mt][0], ah[mt][1], ah[mt][2], ah[mt][3],
                        aAd[mt] + kswzA);
            #pragma unroll
            for (int nb = 0; nb < 2; ++nb) {
                uint32_t r0, r1, r2, r3;
                LDSM_X4(r0, r1, r2, r3, bBase + bOffRow[nb] + kswzB);
                bh[2 * nb][0] = r0; bh[2 * nb][1] = r1;
                bh[2 * nb + 1][0] = r2; bh[2 * nb + 1][1] = r3;
            }
            #pragma unroll
            for (int mt = 0; mt < 2; ++mt)
                #pragma unroll
                for (int nt = 0; nt < 4; ++nt)
                    MMA16816F16(acc[mt][nt], ah[mt], bh[nt]);
        }

        __syncthreads();         // all reads of buf[ch&1] done
        if (ch + 2 < NCHUNK) {   // refill with chunk ch+2
            const uint4* gh = (const uint4*)d_eh + (size_t)(ch + 2) * NCH * 16;
            #pragma unroll
            for (int it = 0; it < 4; ++it) {
                int f = it * NT + tid;
                int r = f >> 4, u = f & 15;
                uint32_t off = (uint32_t)r * 256 + (uint32_t)((u ^ (r & 7)) << 4);
                CP_ASYNC16(bBase + off, gh + f);
            }
        }
        CP_COMMIT();             // keep group accounting aligned

        // ---- scoring: m' = e2c - acc (positive), col in low 9 bits ----
        const int colb = ch * NCH + wn * 32 + qc * 2;
        float he2c[8];
        #pragma unroll
        for (int nt = 0; nt < 4; ++nt) {
            he2c[nt * 2]     = e2cs[colb + nt * 8];
            he2c[nt * 2 + 1] = e2cs[colb + nt * 8 + 1];
        }
        #pragma unroll
        for (int mt = 0; mt < 2; ++mt) {
            #pragma unroll
            for (int rh = 0; rh < 2; ++rh) {
                const int s = mt * 2 + rh;
                uint32_t k1 = key1[s], k2 = key2[s];
                #pragma unroll
                for (int nt = 0; nt < 4; ++nt) {
                    #pragma unroll
                    for (int cc = 0; cc < 2; ++cc) {
                        float v = __fsub_rn(he2c[nt * 2 + cc],
                                            acc[mt][nt][rh * 2 + cc]);
                        uint32_t k = (__float_as_uint(v) & 0xFFFFFE00u)
                                   | (uint32_t)(colb + nt * 8 + cc);
                        k2 = umin(k2, umax(k1, k));
                        k1 = umin(k1, k);
                    }
                }
                key1[s] = k1; key2[s] = k2;
            }
        }
    }

    // ---- shuffle-merge across qc lanes, write slots ----
    #pragma unroll
    for (int s = 0; s < 4; ++s) {
        uint32_t k1 = key1[s], k2 = key2[s];
        #pragma unroll
        for (int m = 1; m <= 2; m <<= 1) {
            uint32_t o1 = __shfl_xor_sync(0xffffffffu, k1, m);
            uint32_t o2 = __shfl_xor_sync(0xffffffffu, k2, m);
            k2 = umin(umax(k1, o1), umin(k2, o2));
            k1 = umin(k1, o1);
        }
        if (qc == 0) {
            int row = wm * 32 + (s >> 1) * 16 + qr + (s & 1) * 8;
            slots[row * 5 + wn * 2 + 0] = k1;
            slots[row * 5 + wn * 2 + 1] = k2;
        }
    }
    __syncthreads();

    // ---- per-row merge of 4 slot keys; margin test; d recovery ----
    if (tid < TM) {
        uint32_t k1 = ~0u, k2 = ~0u;
        #pragma unroll
        for (int i = 0; i < 4; ++i) {
            uint32_t k = slots[tid * 5 + i];
            k2 = umin(k2, umax(k1, k));
            k1 = umin(k1, k);
        }
        sidx[tid] = (int)(k1 & 0x1FFu);
        float m1 = __uint_as_float(k1 & 0xFFFFFE00u);
        float m2 = __uint_as_float(k2 & 0xFFFFFE00u);
        dval[tid] = __fmaf_rn(__fsub_rn(m1, 512.0f), UNSC9, x2s[tid]);
        if (!(m2 - m1 > MARGIN_S)) {
            int pos = atomicAdd(flagc, 1);
            flagl[pos] = tid;
        }
    }
    __syncthreads();

    // ---- exact rescore (R1-replica) — staging over dead A+B regions ----
    const int nflag = *flagc;
    for (int base = 0; base < nflag; base += 16) {
        const int gcount = min(nflag - base, 16);
        if (tid < 16) rrow[tid] = ~0ull;
        for (int cc2 = 0; cc2 < 4; ++cc2) {
            __syncthreads();
            for (int i = tid; i < 128 * 32; i += NT) {
                int r = i >> 5, c4 = i & 31;
                float4 v = ((const float4*)emb)[(size_t)(cc2 * 128 + r) * 32 + c4];
                *(float4*)(smem + OFF_ESTG + r * 512 + ((c4 ^ (r & 31)) << 4)) = v;
            }
            __syncthreads();
            for (int p = tid; p < gcount * 128; p += NT) {
                int fi = p >> 7, c = p & 127;
                int r = flagl[base + fi];
                const float2* xr = (const float2*)x
                                 + (size_t)(row0 + r) * 64;   // warp-broadcast
                const unsigned char* eb = smem + OFF_ESTG + (size_t)c * 512;
                const uint32_t cm = (uint32_t)(c & 31);
                float evn = 0.f, od = 0.f;
                #pragma unroll 8
                for (int l = 0; l < 64; ++l) {
                    float2 xv = xr[l];
                    float2 ev = *(const float2*)(eb
                        + (((uint32_t)(l >> 1) ^ cm) << 4) + (l & 1) * 8);
                    evn = __fmaf_rn(xv.x, ev.x, evn);
                    od  = __fmaf_rn(xv.y, ev.y, od);
                }
                float dot = __fadd_rn(evn, od);
                float d = __fadd_rn(__fsub_rn(x2s[r], __fmul_rn(2.0f, dot)),
                                    e2s[cc2 * 128 + c]);
                ull k = ((ull)__float_as_uint(d) << 32)
                      | (unsigned)(cc2 * 128 + c);
                atomicMin(&rrow[fi], k);
            }
        }
        __syncthreads();
        if (tid < gcount) {
            int r = flagl[base + tid];
            sidx[r] = (int)(rrow[tid] & 0xffffffffu);
            dval[r] = __uint_as_float((uint32_t)(rrow[tid] >> 32));
        }
        __syncthreads();
    }

    // ---- histogram: direct global RED ----
    if (tid < TM) atomicAdd(&d_hist[sidx[tid]], 1u);

    // ---- out0: coalesced gather ----
    #pragma unroll
    for (int it = 0; it < 16; ++it) {
        int f = it * NT + tid;              // 0..4095
        int r = f >> 5, c = f & 31;
        float4 e = ((const float4*)emb)[(size_t)sidx[r] * 32 + c];
        ((float4*)out0)[(size_t)(row0 + r) * 32 + c] = e;
    }

    // ---- out1/out2 from recovered d ----
    if (tid < TM) {
        float s = dval[tid];
        out1[row0 + tid] = s;
        out2[row0 + tid] = s;
    }
}

// ---------------- entropy --------------------------------------------------
__global__ void vq_entropy(float* __restrict__ out_ent, float invRows) {
    __shared__ float red[KTOT];
    int t = threadIdx.x;
    float c = (float)d_hist[t];
    float p = c * invRows;
    red[t] = (p > 0.f) ? p * logf(p) : 0.f;
    __syncthreads();
    #pragma unroll
    for (int s = KTOT / 2; s > 0; s >>= 1) {
        if (t < s) red[t] += red[t + s];
        __syncthreads();
    }
    if (t == 0) *out_ent = -red[0];
}

// Profiler-alignment no-op: ncu captures launch index 3; with the order
// [nop, nop, prep, main, entropy], index 3 = vq_main.
__global__ void vq_nop() {}

extern "C" void kernel_launch(void* const* d_in, const int* in_sizes, int n_in,
                              void* d_out, int out_size)
{
    const float* x   = (const float*)d_in[0];
    const float* emb = (const float*)d_in[1];
    const int rows = in_sizes[0] / LVEC;

    float* out0 = (float*)d_out;
    float* out1 = out0 + (size_t)rows * LVEC;
    float* out2 = out1 + rows;
    float* oent = out2 + rows;

    cudaFuncSetAttribute(vq_main, cudaFuncAttributeMaxDynamicSharedMemorySize,
                         SMEM_BYTES);

    vq_nop<<<1, 32>>>();
    vq_nop<<<1, 32>>>();
    vq_prep<<<64, 256>>>(emb);
    vq_main<<<rows / TM, NT, SMEM_BYTES>>>(x, emb, out0, out1, out2);
    vq_entropy<<<1, KTOT>>>(oent, 1.0f / (float)rows);
}